// round 12
// baseline (speedup 1.0000x reference)
#include <cuda_runtime.h>

// TSM temporal shift: x shape (bt=128, c=96, h=56, w=56), N_FRAME=8, fold=32.
// out[b,t, 0:32] = x[b,t+1, 0:32]  (zero at t=7)
// out[b,t,32:64] = x[b,t-1,32:64]  (zero at t=0)
// out[b,t,64:96] = x[b,t,  64:96]
//
// R12: branchless chunk addressing (R9) at plane granularity (R2) -> max
// occupancy corner (low regs, 8 CTAs/SM) with warp-uniform delta selection.
// 384 uniform chunks (bt x group, 32 planes each) x 32 sub-CTAs; each CTA
// copies 784 contiguous float4 with 3 front-batched LDG.128.CS + 16-lane tail.
// Kernel is HBM-roofline-bound (~76% DRAM sustained across all variants).

#define C_DIM      96
#define N_FRAME    8
#define HW4        784            // 56*56/4
#define CHUNK_F4   25088          // 32 planes * 784
#define DELTA      ((long)C_DIM * HW4)   // 96 planes in float4 units

__global__ __launch_bounds__(256) void tsm_shift_kernel(
    const float4* __restrict__ x, float4* __restrict__ out)
{
    const int bid   = blockIdx.x;          // 0..12287
    const int chunk = bid >> 5;            // 0..383  = bt*3 + g
    const int sub   = bid & 31;
    const int g     = chunk % 3;           // channel group
    const int bt    = chunk / 3;
    const int t     = bt & (N_FRAME - 1);

    // Uniform per-CTA source delta / zero flag (warp-uniform, no divergence).
    long delta = 0;
    bool zero = false;
    if (g == 0)      { if (t < N_FRAME - 1) delta =  DELTA; else zero = true; }
    else if (g == 1) { if (t > 0)           delta = -DELTA; else zero = true; }

    const long base = (long)chunk * CHUNK_F4 + (long)sub * HW4;
    float4* dst = out + base;
    const float4* src = x + base + delta;

    const int tid = threadIdx.x;
    const bool tail = (tid < HW4 - 3 * 256);   // tid < 16

    if (!zero) {
        float4 v0 = __ldcs(src + tid);
        float4 v1 = __ldcs(src + tid + 256);
        float4 v2 = __ldcs(src + tid + 512);
        float4 v3;
        if (tail) v3 = __ldcs(src + tid + 768);
        __stcs(dst + tid,       v0);
        __stcs(dst + tid + 256, v1);
        __stcs(dst + tid + 512, v2);
        if (tail) __stcs(dst + tid + 768, v3);
    } else {
        const float4 z = make_float4(0.f, 0.f, 0.f, 0.f);
        __stcs(dst + tid,       z);
        __stcs(dst + tid + 256, z);
        __stcs(dst + tid + 512, z);
        if (tail) __stcs(dst + tid + 768, z);
    }
}

extern "C" void kernel_launch(void* const* d_in, const int* in_sizes, int n_in,
                              void* d_out, int out_size)
{
    const float4* x = (const float4*)d_in[0];
    float4* out = (float4*)d_out;
    tsm_shift_kernel<<<12288, 256>>>(x, out);   // 384 chunks * 32 CTAs
}

// round 13
// speedup vs baseline: 1.0121x; 1.0121x over previous
#include <cuda_runtime.h>

// TSM temporal shift: x shape (bt=128, c=96, h=56, w=56), N_FRAME=8, fold=32.
// out[b,t,c] = x[b,t+1,c] for c in [0,32)   (zero at t=7)
// out[b,t,c] = x[b,t-1,c] for c in [32,64)  (zero at t=0)
// out[b,t,c] = x[b,t,c]   for c in [64,96)
//
// FINAL (R13): HBM-roofline-bound. Four structurally distinct variants
// (occ 58-81%, MLP 3-8, plane/pair/chunk granularity) all measure
// 39.9-40.0us kernel @ 76% DRAM (~6.0 TB/s counter, ~7.4 TB/s effective);
// traffic (295MB) is irreducible and TMA hits the same LTS cap. This is the
// best-wall-time variant: one-shot grid, 2 consecutive planes per CTA, all
// 8 LDG.128.CS front-batched before any STG.CS.

#define C_DIM     96
#define N_FRAME   8
#define FOLD      32
#define HW4       784          // 56*56/4
#define N_PLANES  12288        // 128*96

__device__ __forceinline__ const float4* src_of(const float4* x, int plane, bool& zero)
{
    const int c = plane % C_DIM;
    const int t = (plane / C_DIM) % N_FRAME;
    const float4* s = x + (size_t)plane * HW4;
    zero = false;
    if (c < FOLD) {
        if (t < N_FRAME - 1) s += (size_t)C_DIM * HW4;     // read t+1
        else zero = true;
    } else if (c < 2 * FOLD) {
        if (t > 0) s -= (size_t)C_DIM * HW4;               // read t-1
        else zero = true;
    }
    return s;
}

__global__ __launch_bounds__(256, 6) void tsm_shift_kernel(
    const float4* __restrict__ x, float4* __restrict__ out)
{
    const int p0 = blockIdx.x * 2;
    const int p1 = p0 + 1;
    const int tid = threadIdx.x;
    const bool tail = (tid < HW4 - 3 * 256);               // tid < 16

    bool z0, z1;
    const float4* s0 = src_of(x, p0, z0);
    const float4* s1 = src_of(x, p1, z1);
    float4* d0 = out + (size_t)p0 * HW4;
    float4* d1 = out + (size_t)p1 * HW4;

    const float4 zv = make_float4(0.f, 0.f, 0.f, 0.f);
    float4 v0 = zv, v1 = zv, v2 = zv, v3 = zv;
    float4 u0 = zv, u1 = zv, u2 = zv, u3 = zv;

    // Front-batch all loads (up to 8 independent LDG.128.CS per thread).
    if (!z0) {
        v0 = __ldcs(s0 + tid);
        v1 = __ldcs(s0 + tid + 256);
        v2 = __ldcs(s0 + tid + 512);
        if (tail) v3 = __ldcs(s0 + tid + 768);
    }
    if (!z1) {
        u0 = __ldcs(s1 + tid);
        u1 = __ldcs(s1 + tid + 256);
        u2 = __ldcs(s1 + tid + 512);
        if (tail) u3 = __ldcs(s1 + tid + 768);
    }

    // Then all stores.
    __stcs(d0 + tid,       v0);
    __stcs(d0 + tid + 256, v1);
    __stcs(d0 + tid + 512, v2);
    if (tail) __stcs(d0 + tid + 768, v3);
    __stcs(d1 + tid,       u0);
    __stcs(d1 + tid + 256, u1);
    __stcs(d1 + tid + 512, u2);
    if (tail) __stcs(d1 + tid + 768, u3);
}

extern "C" void kernel_launch(void* const* d_in, const int* in_sizes, int n_in,
                              void* d_out, int out_size)
{
    const float4* x = (const float4*)d_in[0];
    float4* out = (float4*)d_out;
    tsm_shift_kernel<<<N_PLANES / 2, 256>>>(x, out);   // 6144 CTAs, 2 planes each
}